// round 16
// baseline (speedup 1.0000x reference)
#include <cuda_runtime.h>
#include <math.h>
#include <stdint.h>
#include <stddef.h>

#define S 64
#define V 50257
#define H 512
#define TT 8192

#define STRIDE ((size_t)S * (size_t)TT)               // 524288
#define OFF_XI ((size_t)3 * STRIDE)                   // 1572864
#define OFF_LOGZ (OFF_XI + (size_t)(TT - 1) * S * S)  // 35123200

// libdevice accurate transcendentals (immune to --use_fast_math remapping;
// bitwise-identical to what XLA emits through NVVM/libdevice).
extern "C" __device__ float __nv_expf(float);
extern "C" __device__ float __nv_logf(float);

// ---------------- scratch (__device__ globals) ----------------
__device__ float g_AT[H * S];                    // relu(state_emb) transposed [h][s], fp32
__device__ float g_translog[S * S];
__device__ float g_logT[S * S];                  // row-major [i][j]
__device__ float g_initlp[S];
__device__ float g_logitsR[(size_t)S * V];       // [s][v]
__device__ float g_LSEmax[S];
__device__ float g_LSEls[S];
__device__ float g_emit[TT * S];                 // [t][s]
__device__ float g_abuf[TT * S];                 // log_alpha
__device__ float g_bbuf[TT * S];                 // log_beta
__device__ float g_logZf[1];

__device__ __forceinline__ float4 ld4(const float* p) {
    return *reinterpret_cast<const float4*>(p);
}

// Lane-0 association of a 32-leaf shfl tree computed on a lane PAIR
// (lane^1 holds p_{k+16} for this lane's p_k). Same value on both lanes.
__device__ __forceinline__ float tree32_pair(const float* p) {
    float q[16];
    #pragma unroll
    for (int r = 0; r < 16; ++r) q[r] = __shfl_xor_sync(0xffffffffu, p[r], 1);
    float u[16];
    #pragma unroll
    for (int r = 0; r < 16; ++r) u[r] = p[r] + q[r];
    float v[8];
    #pragma unroll
    for (int r = 0; r < 8; ++r) v[r] = u[r] + u[r + 8];
    float w[4];
    #pragma unroll
    for (int r = 0; r < 4; ++r) w[r] = v[r] + v[r + 4];
    float y0 = w[0] + w[2];
    float y1 = w[1] + w[3];
    return y0 + y1;
}

__device__ __forceinline__ double dtree32_warp(double p) {
    #pragma unroll
    for (int off = 16; off; off >>= 1) p += __shfl_xor_sync(0xffffffffu, p, off);
    return __shfl_sync(0xffffffffu, p, 0);
}
__device__ __forceinline__ float max32_warp(float m) {
    #pragma unroll
    for (int off = 16; off; off >>= 1) m = fmaxf(m, __shfl_xor_sync(0xffffffffu, m, off));
    return m;
}

// ---------------- 1. relu(state_emb) transposed (fp32) ----------------
__global__ void k_prepAT(const float* __restrict__ emb) {   // <<<128,256>>>
    int idx = blockIdx.x * 256 + threadIdx.x;
    int h = idx >> 6, s = idx & 63;
    float v = emb[(size_t)s * H + h];
    g_AT[idx] = v > 0.0f ? v : 0.0f;
}

// ---------------- 2. transition logits: DOUBLE-EXACT dot, round once ----------------
__global__ void k_trans(const float* __restrict__ W, const float* __restrict__ b,
                        const float* __restrict__ q) {      // <<<1024,128>>>
    __shared__ float qs[H];
    int tid = threadIdx.x;
    for (int i = tid; i < H; i += 128) qs[i] = q[i];
    __syncthreads();
    int warp = tid >> 5, lane = tid & 31;
    int r = blockIdx.x * 4 + warp;
    const float* wr = W + (size_t)r * H;
    double acc = 0.0;
    #pragma unroll
    for (int u = 0; u < 16; ++u) {
        int k = lane + u * 32;
        acc = fma((double)wr[k], (double)qs[k], acc);
    }
    acc = dtree32_warp(acc);
    if (lane == 0) g_translog[r] = (float)acc + b[r];
}

// ---------------- 3. row log-softmax: exps fp32, sum in DOUBLE ----------------
__global__ void k_softmax(const float* __restrict__ initial_param) {  // <<<65,64>>>
    __shared__ float xs[S], es[S];
    __shared__ float redm, redls;
    int r = blockIdx.x, tid = threadIdx.x;
    float x = (r < 64) ? g_translog[r * 64 + tid] : initial_param[tid];
    xs[tid] = x;
    __syncthreads();
    if (tid == 0) {
        float m = -1e30f;
        #pragma unroll
        for (int k = 0; k < 64; ++k) m = fmaxf(m, xs[k]);
        redm = m;
    }
    __syncthreads();
    float m = redm;
    float sh = x - m;
    es[tid] = __nv_expf(sh);
    __syncthreads();
    if (tid == 0) {
        double s = 0.0;
        #pragma unroll
        for (int k = 0; k < 64; ++k) s += (double)es[k];   // exact sum
        redls = (float)log(s);                              // correctly-rounded log(sum)
    }
    __syncthreads();
    float o = sh - redls;
    if (r < 64) g_logT[r * 64 + tid] = o;
    else        g_initlp[tid] = o;
}

// ---------------- 4. emission GEMM: PURE FP32 FFMA (k ascending, single acc) ----------------
__global__ void __launch_bounds__(256) k_gemm(const float* __restrict__ emis_W,
                                              const float* __restrict__ emis_b) {  // <<<786,256>>>
    __shared__ __align__(16) float WshT[64][68];   // [k][v]
    __shared__ __align__(16) float Ash[64 * 64];   // [k][s] flat
    int tid = threadIdx.x;
    int v0 = blockIdx.x * 64;
    int c = tid & 15;   // s-quad
    int r = tid >> 4;   // v-quad
    float acc[4][4];
    #pragma unroll
    for (int i = 0; i < 4; ++i)
        #pragma unroll
        for (int jj = 0; jj < 4; ++jj) acc[i][jj] = 0.0f;

    for (int h0 = 0; h0 < H; h0 += 64) {
        const float4* src = (const float4*)(g_AT + h0 * 64);
        float4* dst = (float4*)Ash;
        for (int idx = tid; idx < 1024; idx += 256) dst[idx] = src[idx];
        #pragma unroll
        for (int p = 0; p < 4; ++p) {
            int v = (tid >> 4) + p * 16;
            int vv = v0 + v; if (vv >= V) vv = V - 1;
            int k4 = (tid & 15) * 4;
            float4 w = ld4(emis_W + (size_t)vv * H + h0 + k4);
            WshT[k4 + 0][v] = w.x; WshT[k4 + 1][v] = w.y;
            WshT[k4 + 2][v] = w.z; WshT[k4 + 3][v] = w.w;
        }
        __syncthreads();
        #pragma unroll 8
        for (int k = 0; k < 64; ++k) {
            float4 a4 = ld4(Ash + k * 64 + c * 4);
            float4 w4 = ld4(&WshT[k][r * 4]);
            acc[0][0] = fmaf(w4.x, a4.x, acc[0][0]); acc[0][1] = fmaf(w4.x, a4.y, acc[0][1]);
            acc[0][2] = fmaf(w4.x, a4.z, acc[0][2]); acc[0][3] = fmaf(w4.x, a4.w, acc[0][3]);
            acc[1][0] = fmaf(w4.y, a4.x, acc[1][0]); acc[1][1] = fmaf(w4.y, a4.y, acc[1][1]);
            acc[1][2] = fmaf(w4.y, a4.z, acc[1][2]); acc[1][3] = fmaf(w4.y, a4.w, acc[1][3]);
            acc[2][0] = fmaf(w4.z, a4.x, acc[2][0]); acc[2][1] = fmaf(w4.z, a4.y, acc[2][1]);
            acc[2][2] = fmaf(w4.z, a4.z, acc[2][2]); acc[2][3] = fmaf(w4.z, a4.w, acc[2][3]);
            acc[3][0] = fmaf(w4.w, a4.x, acc[3][0]); acc[3][1] = fmaf(w4.w, a4.y, acc[3][1]);
            acc[3][2] = fmaf(w4.w, a4.z, acc[3][2]); acc[3][3] = fmaf(w4.w, a4.w, acc[3][3]);
        }
        __syncthreads();
    }
    #pragma unroll
    for (int i = 0; i < 4; ++i) {
        int vv = v0 + r * 4 + i;
        if (vv < V) {
            float bb = emis_b[vv];
            #pragma unroll
            for (int jj = 0; jj < 4; ++jj)
                g_logitsR[(size_t)(c * 4 + jj) * V + vv] = acc[i][jj] + bb;
        }
    }
}

// ---------------- 5. LSE over V per state: exps fp32, sum in DOUBLE ----------------
__global__ void __launch_bounds__(1024) k_lse() {    // <<<64,1024>>>
    __shared__ float wredf[32];
    __shared__ double wredd[32];
    __shared__ float bval;
    int s = blockIdx.x, tid = threadIdx.x;
    int lane = tid & 31, warp = tid >> 5;
    const float* row = g_logitsR + (size_t)s * V;

    float m = -1e30f;
    for (int v = tid; v < V; v += 1024) m = fmaxf(m, row[v]);
    m = max32_warp(m);
    if (lane == 0) wredf[warp] = m;
    __syncthreads();
    if (tid < 32) {
        float mm = max32_warp(wredf[tid]);
        if (tid == 0) bval = mm;
    }
    __syncthreads();
    m = bval;

    double acc = 0.0;
    for (int v = tid; v < V; v += 1024) acc += (double)__nv_expf(row[v] - m);
    acc = dtree32_warp(acc);
    if (lane == 0) wredd[warp] = acc;
    __syncthreads();
    if (tid < 32) {
        double p = wredd[tid];
        p = dtree32_warp(p);
        if (tid == 0) {
            g_LSEmax[s] = m;
            g_LSEls[s] = (float)log(p);      // correctly-rounded log(sum)
        }
    }
}

// ---------------- 6. emit[t][s] = fl(fl(logit - max) - logsum) ----------------
__global__ void k_emit(const int* __restrict__ ids) {   // <<<2048,256>>>
    int idx = blockIdx.x * 256 + threadIdx.x;
    int t = idx >> 6, s = idx & 63;
    int w = ids[t];
    float e = (g_logitsR[(size_t)s * V + w] - g_LSEmax[s]) - g_LSEls[s];
    g_emit[idx] = e;
}

// ---------------- 7. faithful scans, XLA reduction-emitter associations ----------------
// fwd (column reduce): p_y = e_y + e_{y+32}, then 32-leaf tree
// bwd (row reduce, vec2): p_k = e_{2k} + e_{2k+1}, then 32-leaf tree
__global__ void __launch_bounds__(128, 1) k_scan() {   // <<<2,128>>>
    __shared__ __align__(16) float Tsh[64 * 66];
    __shared__ __align__(16) float vb[2][64];
    int tid = threadIdx.x;
    int j = tid >> 1, half = tid & 1;

    if (blockIdx.x == 0) {
        // ---------- forward ----------
        for (int idx = tid; idx < 4096; idx += 128) {
            int i = idx >> 6, c = idx & 63;
            Tsh[c * 66 + i] = g_logT[idx];       // Tsh[col][i]
        }
        if (tid < 64) {
            float a0 = g_initlp[tid] + g_emit[tid];
            vb[0][tid] = a0;
            g_abuf[tid] = a0;
        }
        const float* Trow = &Tsh[j * 66];
        int kb = half * 16;
        float ecur[4];
        #pragma unroll
        for (int u = 0; u < 4; ++u) ecur[u] = g_emit[(1 + u) * 64 + j];
        __syncthreads();

        for (int tb = 1; tb < TT; tb += 4) {
            #pragma unroll
            for (int u = 0; u < 4; ++u) {
                int t = tb + u;
                const float* pv = vb[(t + 1) & 1];
                float A1[16], A2[16];
                float m = -1e30f;
                #pragma unroll
                for (int r = 0; r < 16; ++r) {
                    int k = kb + r;
                    float a1 = pv[k] + Trow[k];
                    float a2 = pv[k + 32] + Trow[k + 32];
                    A1[r] = a1; A2[r] = a2;
                    m = fmaxf(m, fmaxf(a1, a2));
                }
                m = fmaxf(m, __shfl_xor_sync(0xffffffffu, m, 1));
                float p[16];
                #pragma unroll
                for (int r = 0; r < 16; ++r)
                    p[r] = __nv_expf(A1[r] - m) + __nv_expf(A2[r] - m);  // e_y + e_{y+32}
                float sum = tree32_pair(p);
                float nj = __nv_logf(sum);
                nj = nj + m;
                nj = nj + ecur[u];
                int tp = t + 4; if (tp > TT - 1) tp = TT - 1;
                ecur[u] = g_emit[tp * 64 + j];
                if (t < TT) {
                    vb[t & 1][j] = nj;
                    g_abuf[t * 64 + j] = nj;
                }
                __syncthreads();
            }
        }
    } else {
        // ---------- backward ----------
        for (int idx = tid; idx < 4096; idx += 128)
            Tsh[(idx >> 6) * 66 + (idx & 63)] = g_logT[idx];   // Tsh[row][j]
        int i = j;
        if (tid < 64) {
            g_bbuf[(TT - 1) * 64 + tid] = 0.0f;
            vb[1][tid] = g_emit[(TT - 1) * 64 + tid] + 0.0f;   // w = e + beta(=0)
        }
        const float* Trow = &Tsh[i * 66];
        int jb = half * 32;
        float ecur[4];
        #pragma unroll
        for (int u = 0; u < 4; ++u) ecur[u] = g_emit[(TT - 2 - u) * 64 + i];
        __syncthreads();

        for (int tb = TT - 2; tb >= 0; tb -= 4) {
            #pragma unroll
            for (int u = 0; u < 4; ++u) {
                int t = tb - u;
                const float* wv = vb[(t + 1) & 1];
                float A1[16], A2[16];
                float m = -1e30f;
                #pragma unroll
                for (int r = 0; r < 16; ++r) {
                    int j0 = jb + 2 * r;
                    float a1 = Trow[j0] + wv[j0];
                    float a2 = Trow[j0 + 1] + wv[j0 + 1];
                    A1[r] = a1; A2[r] = a2;
                    m = fmaxf(m, fmaxf(a1, a2));
                }
                m = fmaxf(m, __shfl_xor_sync(0xffffffffu, m, 1));
                float p[16];
                #pragma unroll
                for (int r = 0; r < 16; ++r)
                    p[r] = __nv_expf(A1[r] - m) + __nv_expf(A2[r] - m);  // e_{2k}+e_{2k+1}
                float sum = tree32_pair(p);
                float bt = __nv_logf(sum);
                bt = bt + m;
                float w = ecur[u] + bt;
                int tp = t - 4; if (tp < 0) tp = 0;
                ecur[u] = g_emit[tp * 64 + i];
                if (t >= 0) {
                    g_bbuf[t * 64 + i] = bt;
                    vb[t & 1][i] = w;
                }
                __syncthreads();
            }
        }
    }
}

// ---------------- 8. logZ: exps fp32, sum in DOUBLE ----------------
__global__ void k_logZ(float* __restrict__ out) {   // <<<1,64>>>
    __shared__ float es[64];
    __shared__ float redm;
    int tid = threadIdx.x;
    float x = g_abuf[(TT - 1) * 64 + tid];
    es[tid] = x;
    __syncthreads();
    if (tid == 0) {
        float m = -1e30f;
        #pragma unroll
        for (int k = 0; k < 64; ++k) m = fmaxf(m, es[k]);
        redm = m;
    }
    __syncthreads();
    float m = redm;
    es[tid] = __nv_expf(x - m);
    __syncthreads();
    if (tid == 0) {
        double s = 0.0;
        #pragma unroll
        for (int k = 0; k < 64; ++k) s += (double)es[k];
        float z = (float)log(s) + m;
        g_logZf[0] = z;
        out[OFF_LOGZ] = z;
    }
}

// ---------------- 9. alpha / beta / gamma outputs (transposed) ----------------
__global__ void k_post(float* __restrict__ out) {   // <<<128,256>>>
    __shared__ float at[64][65], bt[64][65];
    int tid = threadIdx.x;
    int t0 = blockIdx.x * 64;
    for (int idx = tid; idx < 4096; idx += 256) {
        at[idx >> 6][idx & 63] = g_abuf[t0 * 64 + idx];
        bt[idx >> 6][idx & 63] = g_bbuf[t0 * 64 + idx];
    }
    __syncthreads();
    float lz = g_logZf[0];
    for (int e = tid; e < 4096; e += 256) {
        int s = e >> 6, tl = e & 63;
        float la = at[tl][s];
        float lb = bt[tl][s];
        size_t o = (size_t)s * TT + t0 + tl;
        out[o] = la;
        out[STRIDE + o] = lb;
        out[2 * STRIDE + o] = (la + lb) - lz;
    }
}

// ---------------- 10. xi: (((la + logT) + emit) + lb) - logZ ----------------
__global__ void k_xi(float* __restrict__ out) {     // <<<8191,256>>>
    __shared__ float la[64], ze[64], bb[64];
    __shared__ float Tsh[4096];
    int t = blockIdx.x, tid = threadIdx.x;
    for (int idx = tid; idx < 4096; idx += 256) Tsh[idx] = g_logT[idx];
    if (tid < 64) {
        la[tid] = g_abuf[t * 64 + tid];
    } else if (tid < 128) {
        int s2 = tid - 64;
        ze[s2] = g_emit[(t + 1) * 64 + s2];
        bb[s2] = g_bbuf[(t + 1) * 64 + s2];
    }
    __syncthreads();
    float lz = g_logZf[0];
    float* o = out + OFF_XI + (size_t)t * 4096;
    for (int e = tid; e < 4096; e += 256) {
        float v = la[e >> 6] + Tsh[e];
        v = v + ze[e & 63];
        v = v + bb[e & 63];
        o[e] = v - lz;
    }
}

// ---------------- launch ----------------
extern "C" void kernel_launch(void* const* d_in, const int* in_sizes, int n_in,
                              void* d_out, int out_size) {
    const float* query        = (const float*)d_in[0];
    const float* trans_W      = (const float*)d_in[1];
    const float* trans_b      = (const float*)d_in[2];
    const float* initial_par  = (const float*)d_in[3];
    const float* state_emb    = (const float*)d_in[4];
    const float* emis_W       = (const float*)d_in[5];
    const float* emis_b       = (const float*)d_in[6];
    const int*   input_ids    = (const int*)d_in[7];
    float* out = (float*)d_out;

    k_prepAT<<<128, 256>>>(state_emb);
    k_trans<<<1024, 128>>>(trans_W, trans_b, query);
    k_softmax<<<65, 64>>>(initial_par);
    k_gemm<<<(V + 63) / 64, 256>>>(emis_W, emis_b);
    k_lse<<<64, 1024>>>();
    k_emit<<<2048, 256>>>(input_ids);
    k_scan<<<2, 128>>>();
    k_logZ<<<1, 64>>>(out);
    k_post<<<128, 256>>>(out);
    k_xi<<<TT - 1, 256>>>(out);
}

// round 17
// speedup vs baseline: 1.1643x; 1.1643x over previous
#include <cuda_runtime.h>
#include <math.h>
#include <stdint.h>
#include <stddef.h>

#define S 64
#define V 50257
#define H 512
#define TT 8192

#define STRIDE ((size_t)S * (size_t)TT)               // 524288
#define OFF_XI ((size_t)3 * STRIDE)                   // 1572864
#define OFF_LOGZ (OFF_XI + (size_t)(TT - 1) * S * S)  // 35123200

// libdevice accurate transcendentals (immune to --use_fast_math remapping;
// bitwise-identical to what XLA emits through NVVM/libdevice).
extern "C" __device__ float __nv_expf(float);
extern "C" __device__ float __nv_logf(float);

// ---------------- scratch (__device__ globals) ----------------
__device__ float g_AT[H * S];                    // relu(state_emb) transposed [h][s], fp32
__device__ float g_translog[S * S];
__device__ float g_logT[S * S];                  // row-major [i][j]
__device__ float g_initlp[S];
__device__ float g_logitsR[(size_t)S * V];       // [s][v]
__device__ float g_LSEmax[S];
__device__ float g_LSEls[S];
__device__ float g_emit[TT * S];                 // [t][s]
__device__ float g_abuf[TT * S];                 // log_alpha
__device__ float g_bbuf[TT * S];                 // log_beta
__device__ float g_logZf[1];

__device__ __forceinline__ float4 ld4(const float* p) {
    return *reinterpret_cast<const float4*>(p);
}

__device__ __forceinline__ double dtree32_warp(double p) {
    #pragma unroll
    for (int off = 16; off; off >>= 1) p += __shfl_xor_sync(0xffffffffu, p, off);
    return __shfl_sync(0xffffffffu, p, 0);
}
__device__ __forceinline__ float max32_warp(float m) {
    #pragma unroll
    for (int off = 16; off; off >>= 1) m = fmaxf(m, __shfl_xor_sync(0xffffffffu, m, off));
    return m;
}

// ---------------- 1. relu(state_emb) transposed (fp32) ----------------
__global__ void k_prepAT(const float* __restrict__ emb) {   // <<<128,256>>>
    int idx = blockIdx.x * 256 + threadIdx.x;
    int h = idx >> 6, s = idx & 63;
    float v = emb[(size_t)s * H + h];
    g_AT[idx] = v > 0.0f ? v : 0.0f;
}

// ---------------- 2. transition logits: DOUBLE-EXACT dot, round once ----------------
__global__ void k_trans(const float* __restrict__ W, const float* __restrict__ b,
                        const float* __restrict__ q) {      // <<<1024,128>>>
    __shared__ float qs[H];
    int tid = threadIdx.x;
    for (int i = tid; i < H; i += 128) qs[i] = q[i];
    __syncthreads();
    int warp = tid >> 5, lane = tid & 31;
    int r = blockIdx.x * 4 + warp;
    const float* wr = W + (size_t)r * H;
    double acc = 0.0;
    #pragma unroll
    for (int u = 0; u < 16; ++u) {
        int k = lane + u * 32;
        acc = fma((double)wr[k], (double)qs[k], acc);
    }
    acc = dtree32_warp(acc);
    if (lane == 0) g_translog[r] = (float)acc + b[r];
}

// ---------------- 3. row log-softmax: exps fp32, sum in DOUBLE ----------------
__global__ void k_softmax(const float* __restrict__ initial_param) {  // <<<65,64>>>
    __shared__ float xs[S], es[S];
    __shared__ float redm, redls;
    int r = blockIdx.x, tid = threadIdx.x;
    float x = (r < 64) ? g_translog[r * 64 + tid] : initial_param[tid];
    xs[tid] = x;
    __syncthreads();
    if (tid == 0) {
        float m = -1e30f;
        #pragma unroll
        for (int k = 0; k < 64; ++k) m = fmaxf(m, xs[k]);
        redm = m;
    }
    __syncthreads();
    float m = redm;
    float sh = x - m;
    es[tid] = __nv_expf(sh);
    __syncthreads();
    if (tid == 0) {
        double s = 0.0;
        #pragma unroll
        for (int k = 0; k < 64; ++k) s += (double)es[k];   // exact sum
        redls = (float)log(s);                              // correctly-rounded log(sum)
    }
    __syncthreads();
    float o = sh - redls;
    if (r < 64) g_logT[r * 64 + tid] = o;
    else        g_initlp[tid] = o;
}

// ---------------- 4. emission GEMM: PURE FP32 FFMA (k ascending, single acc) ----------------
__global__ void __launch_bounds__(256) k_gemm(const float* __restrict__ emis_W,
                                              const float* __restrict__ emis_b) {  // <<<786,256>>>
    __shared__ __align__(16) float WshT[64][68];   // [k][v]
    __shared__ __align__(16) float Ash[64 * 64];   // [k][s] flat
    int tid = threadIdx.x;
    int v0 = blockIdx.x * 64;
    int c = tid & 15;   // s-quad
    int r = tid >> 4;   // v-quad
    float acc[4][4];
    #pragma unroll
    for (int i = 0; i < 4; ++i)
        #pragma unroll
        for (int jj = 0; jj < 4; ++jj) acc[i][jj] = 0.0f;

    for (int h0 = 0; h0 < H; h0 += 64) {
        const float4* src = (const float4*)(g_AT + h0 * 64);
        float4* dst = (float4*)Ash;
        for (int idx = tid; idx < 1024; idx += 256) dst[idx] = src[idx];
        #pragma unroll
        for (int p = 0; p < 4; ++p) {
            int v = (tid >> 4) + p * 16;
            int vv = v0 + v; if (vv >= V) vv = V - 1;
            int k4 = (tid & 15) * 4;
            float4 w = ld4(emis_W + (size_t)vv * H + h0 + k4);
            WshT[k4 + 0][v] = w.x; WshT[k4 + 1][v] = w.y;
            WshT[k4 + 2][v] = w.z; WshT[k4 + 3][v] = w.w;
        }
        __syncthreads();
        #pragma unroll 8
        for (int k = 0; k < 64; ++k) {
            float4 a4 = ld4(Ash + k * 64 + c * 4);
            float4 w4 = ld4(&WshT[k][r * 4]);
            acc[0][0] = fmaf(w4.x, a4.x, acc[0][0]); acc[0][1] = fmaf(w4.x, a4.y, acc[0][1]);
            acc[0][2] = fmaf(w4.x, a4.z, acc[0][2]); acc[0][3] = fmaf(w4.x, a4.w, acc[0][3]);
            acc[1][0] = fmaf(w4.y, a4.x, acc[1][0]); acc[1][1] = fmaf(w4.y, a4.y, acc[1][1]);
            acc[1][2] = fmaf(w4.y, a4.z, acc[1][2]); acc[1][3] = fmaf(w4.y, a4.w, acc[1][3]);
            acc[2][0] = fmaf(w4.z, a4.x, acc[2][0]); acc[2][1] = fmaf(w4.z, a4.y, acc[2][1]);
            acc[2][2] = fmaf(w4.z, a4.z, acc[2][2]); acc[2][3] = fmaf(w4.z, a4.w, acc[2][3]);
            acc[3][0] = fmaf(w4.w, a4.x, acc[3][0]); acc[3][1] = fmaf(w4.w, a4.y, acc[3][1]);
            acc[3][2] = fmaf(w4.w, a4.z, acc[3][2]); acc[3][3] = fmaf(w4.w, a4.w, acc[3][3]);
        }
        __syncthreads();
    }
    #pragma unroll
    for (int i = 0; i < 4; ++i) {
        int vv = v0 + r * 4 + i;
        if (vv < V) {
            float bb = emis_b[vv];
            #pragma unroll
            for (int jj = 0; jj < 4; ++jj)
                g_logitsR[(size_t)(c * 4 + jj) * V + vv] = acc[i][jj] + bb;
        }
    }
}

// ---------------- 5. LSE over V per state: exps fp32, sum in DOUBLE ----------------
__global__ void __launch_bounds__(1024) k_lse() {    // <<<64,1024>>>
    __shared__ float wredf[32];
    __shared__ double wredd[32];
    __shared__ float bval;
    int s = blockIdx.x, tid = threadIdx.x;
    int lane = tid & 31, warp = tid >> 5;
    const float* row = g_logitsR + (size_t)s * V;

    float m = -1e30f;
    for (int v = tid; v < V; v += 1024) m = fmaxf(m, row[v]);
    m = max32_warp(m);
    if (lane == 0) wredf[warp] = m;
    __syncthreads();
    if (tid < 32) {
        float mm = max32_warp(wredf[tid]);
        if (tid == 0) bval = mm;
    }
    __syncthreads();
    m = bval;

    double acc = 0.0;
    for (int v = tid; v < V; v += 1024) acc += (double)__nv_expf(row[v] - m);
    acc = dtree32_warp(acc);
    if (lane == 0) wredd[warp] = acc;
    __syncthreads();
    if (tid < 32) {
        double p = wredd[tid];
        p = dtree32_warp(p);
        if (tid == 0) {
            g_LSEmax[s] = m;
            g_LSEls[s] = (float)log(p);      // correctly-rounded log(sum)
        }
    }
}

// ---------------- 6. emit[t][s] = fl(fl(logit - max) - logsum) ----------------
__global__ void k_emit(const int* __restrict__ ids) {   // <<<2048,256>>>
    int idx = blockIdx.x * 256 + threadIdx.x;
    int t = idx >> 6, s = idx & 63;
    int w = ids[t];
    float e = (g_logitsR[(size_t)s * V + w] - g_LSEmax[s]) - g_LSEls[s];
    g_emit[idx] = e;
}

// ---------------- 7. faithful scans, 256 threads, BITWISE-IDENTICAL numerics ----------------
// 4 lanes per state (sub = tid&3). Association preservation: after
// u = p + shfl_xor(p,2) and v = u + shfl_xor(u,1), all 4 sub-lanes hold the
// SAME tree values (fp add is bitwise commutative), reproducing tree32_pair's
// exact 32-leaf association. logT lives in registers (constant over steps).
__global__ void __launch_bounds__(256, 1) k_scan() {   // <<<2,256>>>
    __shared__ __align__(16) float vb[2][64];
    int tid = threadIdx.x;
    int j = tid >> 2;          // state 0..63
    int sub = tid & 3;
    const unsigned FULL = 0xffffffffu;

    if (blockIdx.x == 0) {
        // ---------- forward: p_y = e_y + e_{y+32}, y = 8*sub + r ----------
        float T1[8], T2[8];
        int k1 = sub * 8, k2 = k1 + 32;
        #pragma unroll
        for (int r = 0; r < 8; ++r) {
            T1[r] = g_logT[(k1 + r) * 64 + j];
            T2[r] = g_logT[(k2 + r) * 64 + j];
        }
        if (sub == 0) {
            float a0 = g_initlp[j] + g_emit[j];
            vb[0][j] = a0;
            g_abuf[j] = a0;
        }
        float ecur[4];
        #pragma unroll
        for (int u = 0; u < 4; ++u) ecur[u] = g_emit[(1 + u) * 64 + j];
        __syncthreads();

        for (int tb = 1; tb < TT; tb += 4) {
            #pragma unroll
            for (int u = 0; u < 4; ++u) {
                int t = tb + u;
                const float* pv = vb[(t + 1) & 1];
                float4 x0 = ld4(pv + k1), x1 = ld4(pv + k1 + 4);
                float4 x2 = ld4(pv + k2), x3 = ld4(pv + k2 + 4);
                float A1[8], A2[8];
                A1[0] = x0.x + T1[0]; A1[1] = x0.y + T1[1];
                A1[2] = x0.z + T1[2]; A1[3] = x0.w + T1[3];
                A1[4] = x1.x + T1[4]; A1[5] = x1.y + T1[5];
                A1[6] = x1.z + T1[6]; A1[7] = x1.w + T1[7];
                A2[0] = x2.x + T2[0]; A2[1] = x2.y + T2[1];
                A2[2] = x2.z + T2[2]; A2[3] = x2.w + T2[3];
                A2[4] = x3.x + T2[4]; A2[5] = x3.y + T2[5];
                A2[6] = x3.z + T2[6]; A2[7] = x3.w + T2[7];
                // exact max (fmax associative)
                float m = fmaxf(A1[0], A2[0]);
                #pragma unroll
                for (int r = 1; r < 8; ++r) m = fmaxf(m, fmaxf(A1[r], A2[r]));
                m = fmaxf(m, __shfl_xor_sync(FULL, m, 1));
                m = fmaxf(m, __shfl_xor_sync(FULL, m, 2));
                float p[8];
                #pragma unroll
                for (int r = 0; r < 8; ++r)
                    p[r] = __nv_expf(A1[r] - m) + __nv_expf(A2[r] - m);
                float q[8], u8[8];
                #pragma unroll
                for (int r = 0; r < 8; ++r) q[r] = __shfl_xor_sync(FULL, p[r], 2);
                #pragma unroll
                for (int r = 0; r < 8; ++r) u8[r] = p[r] + q[r];     // u_y = p_y + p_{y+16}
                #pragma unroll
                for (int r = 0; r < 8; ++r) q[r] = __shfl_xor_sync(FULL, u8[r], 1);
                float v[8];
                #pragma unroll
                for (int r = 0; r < 8; ++r) v[r] = u8[r] + q[r];     // v_y = u_y + u_{y+8}
                float w0 = v[0] + v[4], w1 = v[1] + v[5];
                float w2 = v[2] + v[6], w3 = v[3] + v[7];
                float y0 = w0 + w2, y1 = w1 + w3;
                float sum = y0 + y1;                                  // identical on all 4 subs
                float nj = __nv_logf(sum);
                nj = nj + m;
                nj = nj + ecur[u];
                int tp = t + 4; if (tp > TT - 1) tp = TT - 1;
                ecur[u] = g_emit[tp * 64 + j];
                if (t < TT && sub == 0) {
                    vb[t & 1][j] = nj;
                    g_abuf[t * 64 + j] = nj;
                }
                __syncthreads();
            }
        }
    } else {
        // ---------- backward: p_k = e_{2k} + e_{2k+1}, k = 8*sub + r ----------
        int i = j;
        float Tr[16];
        int jb = sub * 16;
        #pragma unroll
        for (int r = 0; r < 16; ++r) Tr[r] = g_logT[i * 64 + jb + r];
        if (sub == 0) {
            g_bbuf[(TT - 1) * 64 + i] = 0.0f;
            vb[1][i] = g_emit[(TT - 1) * 64 + i] + 0.0f;   // w = e + beta(=0)
        }
        float ecur[4];
        #pragma unroll
        for (int u = 0; u < 4; ++u) ecur[u] = g_emit[(TT - 2 - u) * 64 + i];
        __syncthreads();

        for (int tb = TT - 2; tb >= 0; tb -= 4) {
            #pragma unroll
            for (int u = 0; u < 4; ++u) {
                int t = tb - u;
                const float* wv = vb[(t + 1) & 1];
                float4 x0 = ld4(wv + jb), x1 = ld4(wv + jb + 4);
                float4 x2 = ld4(wv + jb + 8), x3 = ld4(wv + jb + 12);
                float A[16];
                A[0]  = Tr[0]  + x0.x; A[1]  = Tr[1]  + x0.y;
                A[2]  = Tr[2]  + x0.z; A[3]  = Tr[3]  + x0.w;
                A[4]  = Tr[4]  + x1.x; A[5]  = Tr[5]  + x1.y;
                A[6]  = Tr[6]  + x1.z; A[7]  = Tr[7]  + x1.w;
                A[8]  = Tr[8]  + x2.x; A[9]  = Tr[9]  + x2.y;
                A[10] = Tr[10] + x2.z; A[11] = Tr[11] + x2.w;
                A[12] = Tr[12] + x3.x; A[13] = Tr[13] + x3.y;
                A[14] = Tr[14] + x3.z; A[15] = Tr[15] + x3.w;
                float m = fmaxf(A[0], A[1]);
                #pragma unroll
                for (int r = 2; r < 16; ++r) m = fmaxf(m, A[r]);
                m = fmaxf(m, __shfl_xor_sync(FULL, m, 1));
                m = fmaxf(m, __shfl_xor_sync(FULL, m, 2));
                float p[8];
                #pragma unroll
                for (int r = 0; r < 8; ++r)
                    p[r] = __nv_expf(A[2 * r] - m) + __nv_expf(A[2 * r + 1] - m);
                float q[8], u8[8];
                #pragma unroll
                for (int r = 0; r < 8; ++r) q[r] = __shfl_xor_sync(FULL, p[r], 2);
                #pragma unroll
                for (int r = 0; r < 8; ++r) u8[r] = p[r] + q[r];
                #pragma unroll
                for (int r = 0; r < 8; ++r) q[r] = __shfl_xor_sync(FULL, u8[r], 1);
                float v[8];
                #pragma unroll
                for (int r = 0; r < 8; ++r) v[r] = u8[r] + q[r];
                float w0 = v[0] + v[4], w1 = v[1] + v[5];
                float w2 = v[2] + v[6], w3 = v[3] + v[7];
                float y0 = w0 + w2, y1 = w1 + w3;
                float sum = y0 + y1;
                float bt = __nv_logf(sum);
                bt = bt + m;
                float w = ecur[u] + bt;
                int tp = t - 4; if (tp < 0) tp = 0;
                ecur[u] = g_emit[tp * 64 + i];
                if (t >= 0 && sub == 0) {
                    g_bbuf[t * 64 + i] = bt;
                    vb[t & 1][i] = w;
                }
                __syncthreads();
            }
        }
    }
}

// ---------------- 8. logZ: exps fp32, sum in DOUBLE ----------------
__global__ void k_logZ(float* __restrict__ out) {   // <<<1,64>>>
    __shared__ float es[64];
    __shared__ float redm;
    int tid = threadIdx.x;
    float x = g_abuf[(TT - 1) * 64 + tid];
    es[tid] = x;
    __syncthreads();
    if (tid == 0) {
        float m = -1e30f;
        #pragma unroll
        for (int k = 0; k < 64; ++k) m = fmaxf(m, es[k]);
        redm = m;
    }
    __syncthreads();
    float m = redm;
    es[tid] = __nv_expf(x - m);
    __syncthreads();
    if (tid == 0) {
        double s = 0.0;
        #pragma unroll
        for (int k = 0; k < 64; ++k) s += (double)es[k];
        float z = (float)log(s) + m;
        g_logZf[0] = z;
        out[OFF_LOGZ] = z;
    }
}

// ---------------- 9. alpha / beta / gamma outputs (transposed) ----------------
__global__ void k_post(float* __restrict__ out) {   // <<<128,256>>>
    __shared__ float at[64][65], bt[64][65];
    int tid = threadIdx.x;
    int t0 = blockIdx.x * 64;
    for (int idx = tid; idx < 4096; idx += 256) {
        at[idx >> 6][idx & 63] = g_abuf[t0 * 64 + idx];
        bt[idx >> 6][idx & 63] = g_bbuf[t0 * 64 + idx];
    }
    __syncthreads();
    float lz = g_logZf[0];
    for (int e = tid; e < 4096; e += 256) {
        int s = e >> 6, tl = e & 63;
        float la = at[tl][s];
        float lb = bt[tl][s];
        size_t o = (size_t)s * TT + t0 + tl;
        out[o] = la;
        out[STRIDE + o] = lb;
        out[2 * STRIDE + o] = (la + lb) - lz;
    }
}

// ---------------- 10. xi: (((la + logT) + emit) + lb) - logZ, T cached across t ----------------
__global__ void k_xi(float* __restrict__ out) {     // <<<1024,256>>>
    __shared__ float la[64], ze[64], bb[64];
    __shared__ float Tsh[4096];
    int tid = threadIdx.x;
    for (int idx = tid; idx < 4096; idx += 256) Tsh[idx] = g_logT[idx];
    float lz = g_logZf[0];
    for (int t = blockIdx.x; t < TT - 1; t += 1024) {
        __syncthreads();
        if (tid < 64) {
            la[tid] = g_abuf[t * 64 + tid];
        } else if (tid < 128) {
            int s2 = tid - 64;
            ze[s2] = g_emit[(t + 1) * 64 + s2];
            bb[s2] = g_bbuf[(t + 1) * 64 + s2];
        }
        __syncthreads();
        float* o = out + OFF_XI + (size_t)t * 4096;
        for (int e = tid; e < 4096; e += 256) {
            float v = la[e >> 6] + Tsh[e];
            v = v + ze[e & 63];
            v = v + bb[e & 63];
            o[e] = v - lz;
        }
    }
}

// ---------------- launch ----------------
extern "C" void kernel_launch(void* const* d_in, const int* in_sizes, int n_in,
                              void* d_out, int out_size) {
    const float* query        = (const float*)d_in[0];
    const float* trans_W      = (const float*)d_in[1];
    const float* trans_b      = (const float*)d_in[2];
    const float* initial_par  = (const float*)d_in[3];
    const float* state_emb    = (const float*)d_in[4];
    const float* emis_W       = (const float*)d_in[5];
    const float* emis_b       = (const float*)d_in[6];
    const int*   input_ids    = (const int*)d_in[7];
    float* out = (float*)d_out;

    k_prepAT<<<128, 256>>>(state_emb);
    k_trans<<<1024, 128>>>(trans_W, trans_b, query);
    k_softmax<<<65, 64>>>(initial_par);
    k_gemm<<<(V + 63) / 64, 256>>>(emis_W, emis_b);
    k_lse<<<64, 1024>>>();
    k_emit<<<2048, 256>>>(input_ids);
    k_scan<<<2, 256>>>();
    k_logZ<<<1, 64>>>(out);
    k_post<<<128, 256>>>(out);
    k_xi<<<1024, 256>>>(out);
}